// round 4
// baseline (speedup 1.0000x reference)
#include <cuda_runtime.h>
#include <stdint.h>

// KANLayer: BATCH=512, NUM_IN=NUM_OUT=128, SIZE=16384, K=3, G=5 (8 coefs)
// Outputs (tuple order): y[512,128], pre.T[512,16384], psp.T[512,16384], pac.T[512,16384]
// pre.T[b,s] = x[b, s%128] -> Cox-de-Boor basis hoisted out of the o-loop.
// Tables (coef/mask/scales) read via __ldg; each block runs BB=2 batch-passes
// over the same 40KB table chunk so pass 2 hits L1 (halves L2 table traffic).
// Output stores use evict-first (.cs) since they are never re-read.

#define NUM_IN   128
#define SIZE_T   16384
#define BATCH    512
#define SCHUNK   1024                 // s per block (8 o-rows x 128 i)
#define OCHUNK   (SCHUNK / NUM_IN)    // 8
#define BTILE    8                    // batches per pass
#define BB       2                    // passes per block
#define BQ       4                    // batches per thread per pass
#define THREADS  256
#define NCHUNK   (SIZE_T / SCHUNK)    // 16
#define NBGRP    (BATCH / (BTILE * BB))  // 32

__device__ __forceinline__ void st_cs(float* p, float v)
{
    asm volatile("st.global.cs.f32 [%0], %1;" :: "l"(p), "f"(v) : "memory");
}

// Degree-3 Cox-de-Boor on a uniform grid (knots are a tiled linspace ->
// all denominators are p*h -> division-free recursion).
__device__ __forceinline__ void basis8(float xv, const float* __restrict__ g,
                                       float* __restrict__ Bv)
{
    float e[12];
    const float h = (g[5] - g[0]) * 0.2f;
    e[3] = g[0]; e[4] = g[1]; e[5] = g[2]; e[6] = g[3]; e[7] = g[4]; e[8] = g[5];
    e[2] = g[0] - h;  e[1] = g[0] - 2.0f * h;  e[0] = g[0] - 3.0f * h;
    e[9] = g[5] + h;  e[10] = g[5] + 2.0f * h; e[11] = g[5] + 3.0f * h;
    const float rh = __frcp_rn(h);

    float B[11];
#pragma unroll
    for (int j = 0; j < 11; j++)
        B[j] = (xv >= e[j] && xv < e[j + 1]) ? 1.0f : 0.0f;

#pragma unroll
    for (int p = 1; p <= 3; p++) {
        const float rhp = rh * (p == 1 ? 1.0f : (p == 2 ? 0.5f : (1.0f / 3.0f)));
#pragma unroll
        for (int j = 0; j + p < 11; j++) {
            B[j] = (xv - e[j]) * rhp * B[j] + (e[j + p + 1] - xv) * rhp * B[j + 1];
        }
    }
#pragma unroll
    for (int j = 0; j < 8; j++) Bv[j] = B[j];
}

extern "C" __global__ void __launch_bounds__(THREADS, 4)
kan_main(const float* __restrict__ x,
         const float* __restrict__ scale_b,
         const float* __restrict__ scale_sp,
         const float* __restrict__ coef,
         const float* __restrict__ mask,
         const float* __restrict__ knots,
         float* __restrict__ y,
         float* __restrict__ pre,
         float* __restrict__ psp,
         float* __restrict__ pac)
{
    const int bg    = blockIdx.x >> 4;      // 32 batch groups (16 batches each)
    const int chunk = blockIdx.x & 15;      // 16 s-chunks
    const int sbase = chunk * SCHUNK;

    const int tid  = threadIdx.x;
    const int i    = tid & (NUM_IN - 1);    // s % 128 owned by this thread
    const int slot = tid >> 7;              // 0 / 1

    // knots for this i, loaded once
    float gl[6];
    {
        const float* g = knots + (size_t)i * 6;
#pragma unroll
        for (int m = 0; m < 6; m++) gl[m] = __ldg(g + m);
    }

    const float4* cg = (const float4*)coef;   // 2 float4 per s-row

    for (int bb = 0; bb < BB; bb++) {
        const int b0 = (bg * BB + bb) * BTILE + slot * BQ;

        // ---- per-(b,i) basis + silu, once per pass, reused over all o ----
        float Bv[BQ][8], xv[BQ], sl[BQ], acc[BQ];
#pragma unroll
        for (int q = 0; q < BQ; q++) {
            xv[q]  = __ldg(x + (size_t)(b0 + q) * NUM_IN + i);
            sl[q]  = xv[q] / (1.0f + __expf(-xv[q]));   // silu
            acc[q] = 0.0f;
            basis8(xv[q], gl, Bv[q]);
        }

        const size_t base0 = (size_t)b0 * SIZE_T + (size_t)sbase + i;
        float* p0 = pre + base0;
        float* p1 = psp + base0;
        float* p2 = pac + base0;

        // ---- main loop: 8 o-rows x 4 batches per thread ----
#pragma unroll 2
        for (int o = 0; o < OCHUNK; o++) {
            const int    s   = sbase + o * NUM_IN + i;
            const float4 cA  = __ldg(cg + (size_t)s * 2);
            const float4 cB  = __ldg(cg + (size_t)s * 2 + 1);
            const float  m   = __ldg(mask + s);
            const float  sbv = __ldg(scale_b + s);
            const float  ssv = __ldg(scale_sp + s);
            const int    off = o * NUM_IN;
#pragma unroll
            for (int q = 0; q < BQ; q++) {
                const float sp = (cA.x * Bv[q][0] + cA.y * Bv[q][1]
                                + cA.z * Bv[q][2] + cA.w * Bv[q][3]
                                + cB.x * Bv[q][4] + cB.y * Bv[q][5]
                                + cB.z * Bv[q][6] + cB.w * Bv[q][7]) * m;
                const float pa = sbv * sl[q] + ssv * sp;
                const size_t idx = (size_t)q * SIZE_T + off;
                st_cs(p0 + idx, xv[q]);
                st_cs(p1 + idx, sp);
                st_cs(p2 + idx, pa);
                acc[q] += pa;
            }
        }

        // ---- y[b,i] partial reduction ----
#pragma unroll
        for (int q = 0; q < BQ; q++)
            atomicAdd(y + (size_t)(b0 + q) * NUM_IN + i, acc[q]);
    }
}

extern "C" void kernel_launch(void* const* d_in, const int* in_sizes, int n_in,
                              void* d_out, int out_size)
{
    const float* x    = (const float*)d_in[0];
    const float* sb   = (const float*)d_in[1];
    const float* ss   = (const float*)d_in[2];
    const float* coef = (const float*)d_in[3];
    const float* mask = (const float*)d_in[4];
    const float* kn   = (const float*)d_in[5];

    float* y   = (float*)d_out;
    float* pre = y   + (size_t)BATCH * NUM_IN;
    float* psp = pre + (size_t)BATCH * SIZE_T;
    float* pac = psp + (size_t)BATCH * SIZE_T;

    cudaMemsetAsync(y, 0, (size_t)BATCH * NUM_IN * sizeof(float), 0);
    kan_main<<<NBGRP * NCHUNK, THREADS>>>(x, sb, ss, coef, mask, kn,
                                          y, pre, psp, pac);
}

// round 6
// speedup vs baseline: 1.3704x; 1.3704x over previous
#include <cuda_runtime.h>
#include <stdint.h>

// KANLayer: BATCH=512, NUM_IN=NUM_OUT=128, SIZE=16384, K=3, G=5 (8 coefs)
// Outputs (tuple order): y[512,128], pre.T[512,16384], psp.T[512,16384], pac.T[512,16384]
// pre.T[b,s] = x[b, s%128] -> Cox-de-Boor basis hoisted out of the o-loop.
// R5: R3 shape (grid 1024, BQ=4) + cp.async.bulk staging of the 44KB table
// chunk into SMEM, overlapped with basis computation (no LDG+STS round-trip,
// no first-touch L2 latency inside the mainloop).

#define NUM_IN   128
#define SIZE_T   16384
#define BATCH    512
#define SCHUNK   1024                 // s per block (8 o-rows x 128 i)
#define OCHUNK   (SCHUNK / NUM_IN)    // 8
#define BTILE    8                    // batches per block
#define BQ       4                    // batches per thread
#define THREADS  256
#define NCHUNK   (SIZE_T / SCHUNK)    // 16
#define NBGRP    (BATCH / BTILE)      // 64
#define STAGE_BYTES (SCHUNK * 32 + 3 * SCHUNK * 4)   // 45056

__device__ __forceinline__ uint32_t smem_u32(const void* p)
{
    uint32_t a;
    asm("{ .reg .u64 t; cvta.to.shared.u64 t, %1; cvt.u32.u64 %0, t; }"
        : "=r"(a) : "l"(p));
    return a;
}

__device__ __forceinline__ void bulk_g2s(uint32_t dst, const void* src,
                                         uint32_t bytes, uint32_t bar)
{
    asm volatile(
        "cp.async.bulk.shared::cta.global.mbarrier::complete_tx::bytes "
        "[%0], [%1], %2, [%3];"
        :: "r"(dst), "l"(src), "r"(bytes), "r"(bar) : "memory");
}

// Degree-3 Cox-de-Boor on a uniform grid (knots are a tiled linspace ->
// all denominators are p*h -> division-free recursion).
__device__ __forceinline__ void basis8(float xv, const float* __restrict__ g,
                                       float* __restrict__ Bv)
{
    float e[12];
    const float h = (g[5] - g[0]) * 0.2f;
    e[3] = g[0]; e[4] = g[1]; e[5] = g[2]; e[6] = g[3]; e[7] = g[4]; e[8] = g[5];
    e[2] = g[0] - h;  e[1] = g[0] - 2.0f * h;  e[0] = g[0] - 3.0f * h;
    e[9] = g[5] + h;  e[10] = g[5] + 2.0f * h; e[11] = g[5] + 3.0f * h;
    const float rh = __frcp_rn(h);

    float B[11];
#pragma unroll
    for (int j = 0; j < 11; j++)
        B[j] = (xv >= e[j] && xv < e[j + 1]) ? 1.0f : 0.0f;

#pragma unroll
    for (int p = 1; p <= 3; p++) {
        const float rhp = rh * (p == 1 ? 1.0f : (p == 2 ? 0.5f : (1.0f / 3.0f)));
#pragma unroll
        for (int j = 0; j + p < 11; j++) {
            B[j] = (xv - e[j]) * rhp * B[j] + (e[j + p + 1] - xv) * rhp * B[j + 1];
        }
    }
#pragma unroll
    for (int j = 0; j < 8; j++) Bv[j] = B[j];
}

extern "C" __global__ void __launch_bounds__(THREADS, 4)
kan_main(const float* __restrict__ x,
         const float* __restrict__ scale_b,
         const float* __restrict__ scale_sp,
         const float* __restrict__ coef,
         const float* __restrict__ mask,
         const float* __restrict__ knots,
         float* __restrict__ y,
         float* __restrict__ pre,
         float* __restrict__ psp,
         float* __restrict__ pac)
{
    __shared__ alignas(128) float4 s_coef[SCHUNK * 2];  // 32 KB
    __shared__ float s_sb[SCHUNK];                      //  4 KB
    __shared__ float s_ss[SCHUNK];                      //  4 KB
    __shared__ float s_mk[SCHUNK];                      //  4 KB
    __shared__ alignas(8) uint64_t s_bar;

    const int bg    = blockIdx.x >> 4;      // 64 batch groups
    const int chunk = blockIdx.x & 15;      // 16 s-chunks
    const int sbase = chunk * SCHUNK;
    const int bbase = bg * BTILE;

    const int tid  = threadIdx.x;
    const int i    = tid & (NUM_IN - 1);    // s % 128 owned by this thread
    const int slot = tid >> 7;              // 0 / 1
    const int b0   = bbase + slot * BQ;

    const uint32_t bar = smem_u32(&s_bar);

    if (tid == 0) {
        asm volatile("mbarrier.init.shared::cta.b64 [%0], 1;" :: "r"(bar) : "memory");
    }
    __syncthreads();

    if (tid == 0) {
        asm volatile("mbarrier.arrive.expect_tx.shared::cta.b64 _, [%0], %1;"
                     :: "r"(bar), "r"((uint32_t)STAGE_BYTES) : "memory");
        bulk_g2s(smem_u32(s_coef), coef + (size_t)sbase * 8, SCHUNK * 32, bar);
        bulk_g2s(smem_u32(s_sb),   scale_b  + sbase, SCHUNK * 4, bar);
        bulk_g2s(smem_u32(s_ss),   scale_sp + sbase, SCHUNK * 4, bar);
        bulk_g2s(smem_u32(s_mk),   mask     + sbase, SCHUNK * 4, bar);
    }

    // ---- basis + silu, computed while the bulk copy is in flight ----
    float gl[6];
    {
        const float* g = knots + (size_t)i * 6;
#pragma unroll
        for (int m = 0; m < 6; m++) gl[m] = __ldg(g + m);
    }
    float Bv[BQ][8], xv[BQ], sl[BQ], acc[BQ];
#pragma unroll
    for (int q = 0; q < BQ; q++) {
        xv[q]  = __ldg(x + (size_t)(b0 + q) * NUM_IN + i);
        sl[q]  = xv[q] / (1.0f + __expf(-xv[q]));   // silu
        acc[q] = 0.0f;
        basis8(xv[q], gl, Bv[q]);
    }

    // wait for the staged tables
    asm volatile(
        "{\n\t"
        ".reg .pred P;\n\t"
        "W%=:\n\t"
        "mbarrier.try_wait.parity.acquire.cta.shared::cta.b64 P, [%0], 0;\n\t"
        "@!P bra W%=;\n\t"
        "}"
        :: "r"(bar) : "memory");

    // per-thread output base pointers (advance 128 per o-row)
    const size_t base0 = (size_t)b0 * SIZE_T + (size_t)sbase + i;
    float* p0 = pre + base0;
    float* p1 = psp + base0;
    float* p2 = pac + base0;

    // ---- main loop: 8 o-rows x 4 batches per thread ----
#pragma unroll 2
    for (int o = 0; o < OCHUNK; o++) {
        const int    rl  = o * NUM_IN + i;
        const float4 cA  = s_coef[rl * 2];
        const float4 cB  = s_coef[rl * 2 + 1];
        const float  m   = s_mk[rl];
        const float  sbv = s_sb[rl];
        const float  ssv = s_ss[rl];
        const int    off = o * NUM_IN;
#pragma unroll
        for (int q = 0; q < BQ; q++) {
            const float sp = (cA.x * Bv[q][0] + cA.y * Bv[q][1]
                            + cA.z * Bv[q][2] + cA.w * Bv[q][3]
                            + cB.x * Bv[q][4] + cB.y * Bv[q][5]
                            + cB.z * Bv[q][6] + cB.w * Bv[q][7]) * m;
            const float pa = sbv * sl[q] + ssv * sp;
            const size_t idx = (size_t)q * SIZE_T + off;
            p0[idx] = xv[q];
            p1[idx] = sp;
            p2[idx] = pa;
            acc[q] += pa;
        }
    }

    // ---- y[b,i] partial reduction (one RED per (b,i) per block) ----
#pragma unroll
    for (int q = 0; q < BQ; q++)
        atomicAdd(y + (size_t)(b0 + q) * NUM_IN + i, acc[q]);
}

extern "C" void kernel_launch(void* const* d_in, const int* in_sizes, int n_in,
                              void* d_out, int out_size)
{
    const float* x    = (const float*)d_in[0];
    const float* sb   = (const float*)d_in[1];
    const float* ss   = (const float*)d_in[2];
    const float* coef = (const float*)d_in[3];
    const float* mask = (const float*)d_in[4];
    const float* kn   = (const float*)d_in[5];

    float* y   = (float*)d_out;
    float* pre = y   + (size_t)BATCH * NUM_IN;
    float* psp = pre + (size_t)BATCH * SIZE_T;
    float* pac = psp + (size_t)BATCH * SIZE_T;

    cudaMemsetAsync(y, 0, (size_t)BATCH * NUM_IN * sizeof(float), 0);
    kan_main<<<NBGRP * NCHUNK, THREADS>>>(x, sb, ss, coef, mask, kn,
                                          y, pre, psp, pac);
}